// round 5
// baseline (speedup 1.0000x reference)
#include <cuda_runtime.h>
#include <cuda_bf16.h>
#include <math.h>

#define N_NODES   100000
#define N_EDGES   1600000
#define FEAT      128
#define N_GRAPHS  512
#define N_CLASSES 10

// ---------------- scratch (device globals; referenced ONLY from device code) --
__device__ int   g_deg[N_NODES];
__device__ int   g_off[N_NODES + 1];
__device__ int   g_cur[N_NODES];
__device__ int   g_csr[N_EDGES];
__device__ float g_cnt[N_NODES];

__device__ float g_mean[N_NODES * FEAT];
__device__ float g_hA[N_NODES * FEAT];
__device__ float g_hB[N_NODES * FEAT];

__device__ float    g_gate[N_NODES];
__device__ unsigned g_mu[N_GRAPHS];
__device__ float    g_s[N_GRAPHS];
__device__ float    g_pool[N_GRAPHS * FEAT];

// ---------------- helpers ----------------
__device__ __forceinline__ unsigned float_to_ordered(float f) {
    unsigned b = __float_as_uint(f);
    return (b & 0x80000000u) ? ~b : (b | 0x80000000u);
}
__device__ __forceinline__ float ordered_to_float(unsigned u) {
    unsigned b = (u & 0x80000000u) ? (u ^ 0x80000000u) : ~u;
    return __uint_as_float(b);
}
// select hidden buffer by phase: 0 -> external x, 1 -> g_hA, 2 -> g_hB
__device__ __forceinline__ const float* sel_buf(int sel, const float* xext) {
    return sel == 0 ? xext : (sel == 1 ? (const float*)g_hA : (const float*)g_hB);
}

// ---------------- init ----------------
__global__ void k_init() {
    int i = blockIdx.x * blockDim.x + threadIdx.x;
    if (i < N_NODES) g_deg[i] = 0;
    if (i < N_GRAPHS) { g_mu[i] = 0u; g_s[i] = 0.0f; }
    if (i < N_GRAPHS * FEAT) g_pool[i] = 0.0f;
}

// ---------------- CSR build (split layout: src=ei[0..E), dst=ei[E..2E)) ------
__global__ void k_hist(const int* __restrict__ ei) {
    int e = blockIdx.x * blockDim.x + threadIdx.x;
    if (e < N_EDGES) atomicAdd(&g_deg[ei[N_EDGES + e]], 1);
}

__global__ void k_scan() {   // single block, 1024 threads
    __shared__ int partial[1024];
    const int T = 1024;
    int t = threadIdx.x;
    int chunk = (N_NODES + T - 1) / T;
    int lo = t * chunk;
    int hi = min(lo + chunk, N_NODES);
    int sum = 0;
    for (int i = lo; i < hi; i++) sum += g_deg[i];
    partial[t] = sum;
    __syncthreads();
    for (int d = 1; d < T; d <<= 1) {
        int v = (t >= d) ? partial[t - d] : 0;
        __syncthreads();
        partial[t] += v;
        __syncthreads();
    }
    int run = (t == 0) ? 0 : partial[t - 1];
    for (int i = lo; i < hi; i++) {
        g_off[i] = run;
        g_cur[i] = run;
        g_cnt[i] = fmaxf((float)g_deg[i], 1.0f);
        run += g_deg[i];
    }
    if (t == T - 1) g_off[N_NODES] = run;
}

__global__ void k_scatter(const int* __restrict__ ei) {
    int e = blockIdx.x * blockDim.x + threadIdx.x;
    if (e < N_EDGES) {
        int pos = atomicAdd(&g_cur[ei[N_EDGES + e]], 1);
        g_csr[pos] = ei[e];
    }
}

// ---------------- mean aggregation (atomic-free, 1 block / node) -------------
__global__ void k_agg(const float* __restrict__ xext, int sel) {
    const float* __restrict__ X = sel_buf(sel, xext);
    int node = blockIdx.x;
    int t = threadIdx.x;
    int s = g_off[node], e = g_off[node + 1];
    float acc = 0.0f;
    for (int i = s; i < e; i++) {
        int srcn = g_csr[i];
        acc += __ldg(&X[(size_t)srcn * FEAT + t]);
    }
    g_mean[(size_t)node * FEAT + t] = acc / g_cnt[node];
}

// ---------------- fused GEMM: out = relu(g_mean@W1 + A2@W2 + bias) -----------
// A2/out chosen by sel: sel=0: A2=x,   out=g_hA
//                       sel=1: A2=g_hA, out=g_hB
//                       sel=2: A2=g_hB, out=g_hA
#define BM 64
#define BN 128
#define BK 16
__global__ __launch_bounds__(256) void k_gemm(
    const float* __restrict__ xext,
    const float* __restrict__ W1, const float* __restrict__ W2,
    const float* __restrict__ bias, int sel, int nrows)
{
    const float* __restrict__ A1 = g_mean;
    const float* __restrict__ A2 = sel_buf(sel, xext);
    float* __restrict__ out = (sel == 1) ? g_hB : g_hA;

    __shared__ float As[BK][BM];
    __shared__ float Bs[BK][BN];
    int block_row = blockIdx.x * BM;
    int t  = threadIdx.x;
    int ty = t >> 5;
    int tx = t & 31;

    int arow = t >> 2;
    int acol = (t & 3) * 4;
    int brow = t >> 4;
    int bcol = (t & 15) * 8;

    float acc[8][4];
#pragma unroll
    for (int i = 0; i < 8; i++)
#pragma unroll
        for (int j = 0; j < 4; j++) acc[i][j] = 0.0f;

    for (int phase = 0; phase < 2; phase++) {
        const float* A = phase ? A2 : A1;
        const float* W = phase ? W2 : W1;
        for (int k0 = 0; k0 < FEAT; k0 += BK) {
            int grow = block_row + arow;
            float4 av = make_float4(0.f, 0.f, 0.f, 0.f);
            if (grow < nrows)
                av = *(const float4*)(A + (size_t)grow * FEAT + k0 + acol);
            As[acol + 0][arow] = av.x;
            As[acol + 1][arow] = av.y;
            As[acol + 2][arow] = av.z;
            As[acol + 3][arow] = av.w;

            float4 b0 = *(const float4*)(W + (size_t)(k0 + brow) * BN + bcol);
            float4 b1 = *(const float4*)(W + (size_t)(k0 + brow) * BN + bcol + 4);
            *(float4*)&Bs[brow][bcol]     = b0;
            *(float4*)&Bs[brow][bcol + 4] = b1;
            __syncthreads();

#pragma unroll
            for (int k = 0; k < BK; k++) {
                float a[8], b[4];
                *(float4*)&a[0] = *(const float4*)&As[k][ty * 8];
                *(float4*)&a[4] = *(const float4*)&As[k][ty * 8 + 4];
                *(float4*)&b[0] = *(const float4*)&Bs[k][tx * 4];
#pragma unroll
                for (int i = 0; i < 8; i++)
#pragma unroll
                    for (int j = 0; j < 4; j++)
                        acc[i][j] = fmaf(a[i], b[j], acc[i][j]);
            }
            __syncthreads();
        }
    }

    float bv[4];
    *(float4*)bv = *(const float4*)(bias + tx * 4);
#pragma unroll
    for (int i = 0; i < 8; i++) {
        int r = block_row + ty * 8 + i;
        if (r < nrows) {
            float4 o;
            o.x = fmaxf(acc[i][0] + bv[0], 0.0f);
            o.y = fmaxf(acc[i][1] + bv[1], 0.0f);
            o.z = fmaxf(acc[i][2] + bv[2], 0.0f);
            o.w = fmaxf(acc[i][3] + bv[3], 0.0f);
            *(float4*)(out + (size_t)r * FEAT + tx * 4) = o;
        }
    }
}

// ---------------- gate: g_gate[i] = g_hA[i,:]·gate_w + gate_b ----------------
__global__ void k_gate(const float* __restrict__ gate_w,
                       const float* __restrict__ gate_b) {
    int warp = threadIdx.x >> 5;
    int lane = threadIdx.x & 31;
    int node = blockIdx.x * 8 + warp;
    if (node >= N_NODES) return;
    const float* hr = g_hA + (size_t)node * FEAT;
    float4 hv = *(const float4*)(hr + lane * 4);
    float4 wv = *(const float4*)(gate_w + lane * 4);
    float s = hv.x * wv.x + hv.y * wv.y + hv.z * wv.z + hv.w * wv.w;
#pragma unroll
    for (int d = 16; d > 0; d >>= 1) s += __shfl_xor_sync(0xFFFFFFFFu, s, d);
    if (lane == 0) g_gate[node] = s + gate_b[0];
}

__global__ void k_segmax(const int* __restrict__ batch) {
    int i = blockIdx.x * blockDim.x + threadIdx.x;
    if (i < N_NODES) atomicMax(&g_mu[batch[i]], float_to_ordered(g_gate[i]));
}

__global__ void k_expsum(const int* __restrict__ batch) {
    int i = blockIdx.x * blockDim.x + threadIdx.x;
    if (i < N_NODES) {
        int b = batch[i];
        float m = ordered_to_float(g_mu[b]);
        float e = expf(g_gate[i] - m);
        g_gate[i] = e;
        atomicAdd(&g_s[b], e);
    }
}

__global__ void k_pool(const int* __restrict__ batch) {
    int node = blockIdx.x;
    int t = threadIdx.x;
    int b = batch[node];
    float w = g_gate[node];
    atomicAdd(&g_pool[(size_t)b * FEAT + t], w * g_hA[(size_t)node * FEAT + t]);
}

// ---------------- head ----------------
__global__ void k_head(const float* __restrict__ lin1_w, const float* __restrict__ lin1_b,
                       const float* __restrict__ lin2_w, const float* __restrict__ lin2_b,
                       float* __restrict__ out) {
    int g = blockIdx.x;
    int t = threadIdx.x;
    __shared__ float sp[FEAT];
    __shared__ float so[FEAT];
    __shared__ float lg[N_CLASSES];

    float s = g_s[g];
    float p = (s > 0.0f) ? g_pool[(size_t)g * FEAT + t] / s : 0.0f;
    sp[t] = p;
    __syncthreads();

    float acc = lin1_b[t];
#pragma unroll 8
    for (int k = 0; k < FEAT; k++)
        acc = fmaf(sp[k], lin1_w[(size_t)k * FEAT + t], acc);
    so[t] = fmaxf(acc, 0.0f);
    __syncthreads();

    if (t < N_CLASSES) {
        float a = lin2_b[t];
#pragma unroll 8
        for (int k = 0; k < FEAT; k++)
            a = fmaf(so[k], lin2_w[(size_t)k * N_CLASSES + t], a);
        lg[t] = a;
    }
    __syncthreads();

    if (t == 0) {
        float mx = lg[0];
#pragma unroll
        for (int j = 1; j < N_CLASSES; j++) mx = fmaxf(mx, lg[j]);
        float se = 0.0f;
#pragma unroll
        for (int j = 0; j < N_CLASSES; j++) se += expf(lg[j] - mx);
        float l = logf(se);
#pragma unroll
        for (int j = 0; j < N_CLASSES; j++)
            out[(size_t)g * N_CLASSES + j] = lg[j] - mx - l;
    }
}

// ---------------- launch ----------------
extern "C" void kernel_launch(void* const* d_in, const int* in_sizes, int n_in,
                              void* d_out, int out_size) {
    const float* x      = (const float*)d_in[0];
    const int*   ei     = (const int*)  d_in[1];
    const int*   batch  = (const int*)  d_in[2];
    const float* w1l = (const float*)d_in[3];
    const float* b1  = (const float*)d_in[4];
    const float* w1r = (const float*)d_in[5];
    const float* w2l = (const float*)d_in[6];
    const float* b2  = (const float*)d_in[7];
    const float* w2r = (const float*)d_in[8];
    const float* w3l = (const float*)d_in[9];
    const float* b3  = (const float*)d_in[10];
    const float* w3r = (const float*)d_in[11];
    const float* gate_w = (const float*)d_in[12];
    const float* gate_b = (const float*)d_in[13];
    const float* lin1_w = (const float*)d_in[14];
    const float* lin1_b = (const float*)d_in[15];
    const float* lin2_w = (const float*)d_in[16];
    const float* lin2_b = (const float*)d_in[17];
    float* out = (float*)d_out;

    const int TB = 256;
    int init_elems = N_NODES;
    if (N_GRAPHS * FEAT > init_elems) init_elems = N_GRAPHS * FEAT;

    k_init<<<(init_elems + TB - 1) / TB, TB>>>();
    k_hist<<<(N_EDGES + TB - 1) / TB, TB>>>(ei);
    k_scan<<<1, 1024>>>();
    k_scatter<<<(N_EDGES + TB - 1) / TB, TB>>>(ei);

    int gemm_blocks = (N_NODES + BM - 1) / BM;

    // layer 1: g_hA = relu(mean(x)@w1l + x@w1r + b1)
    k_agg<<<N_NODES, FEAT>>>(x, 0);
    k_gemm<<<gemm_blocks, 256>>>(x, w1l, w1r, b1, 0, N_NODES);
    // layer 2: g_hB = relu(mean(g_hA)@w2l + g_hA@w2r + b2)
    k_agg<<<N_NODES, FEAT>>>(x, 1);
    k_gemm<<<gemm_blocks, 256>>>(x, w2l, w2r, b2, 1, N_NODES);
    // layer 3: g_hA = relu(mean(g_hB)@w3l + g_hB@w3r + b3)
    k_agg<<<N_NODES, FEAT>>>(x, 2);
    k_gemm<<<gemm_blocks, 256>>>(x, w3l, w3r, b3, 2, N_NODES);

    // attentional aggregation over g_hA
    k_gate<<<(N_NODES + 7) / 8, 256>>>(gate_w, gate_b);
    k_segmax<<<(N_NODES + TB - 1) / TB, TB>>>(batch);
    k_expsum<<<(N_NODES + TB - 1) / TB, TB>>>(batch);
    k_pool<<<N_NODES, FEAT>>>(batch);

    // head
    k_head<<<N_GRAPHS, FEAT>>>(lin1_w, lin1_b, lin2_w, lin2_b, out);
}

// round 6
// speedup vs baseline: 1.6728x; 1.6728x over previous
#include <cuda_runtime.h>
#include <cuda_bf16.h>
#include <math.h>

#define N_NODES   100000
#define N_EDGES   1600000
#define FEAT      128
#define N_GRAPHS  512
#define N_CLASSES 10

// ---------------- scratch (device globals; referenced ONLY from device code) --
__device__ int   g_deg[N_NODES];
__device__ int   g_off[N_NODES + 1];
__device__ int   g_cur[N_NODES];
__device__ int   g_csr[N_EDGES];
__device__ float g_cnt[N_NODES];

__device__ float g_mean[N_NODES * FEAT];
__device__ float g_hA[N_NODES * FEAT];
__device__ float g_hB[N_NODES * FEAT];

__device__ float    g_gate[N_NODES];
__device__ unsigned g_mu[N_GRAPHS];
__device__ float    g_s[N_GRAPHS];
__device__ float    g_pool[N_GRAPHS * FEAT];

// ---------------- helpers ----------------
__device__ __forceinline__ unsigned float_to_ordered(float f) {
    unsigned b = __float_as_uint(f);
    return (b & 0x80000000u) ? ~b : (b | 0x80000000u);
}
__device__ __forceinline__ float ordered_to_float(unsigned u) {
    unsigned b = (u & 0x80000000u) ? (u ^ 0x80000000u) : ~u;
    return __uint_as_float(b);
}
__device__ __forceinline__ float tf32r(float x) {   // round-to-nearest tf32
    unsigned r;
    asm("cvt.rna.tf32.f32 %0, %1;" : "=r"(r) : "f"(x));
    return __uint_as_float(r);
}
__device__ __forceinline__ const float* sel_buf(int sel, const float* xext) {
    return sel == 0 ? xext : (sel == 1 ? (const float*)g_hA : (const float*)g_hB);
}
__device__ __forceinline__ void mma_tf32(float* d, const unsigned* a, const unsigned* b) {
    asm volatile(
        "mma.sync.aligned.m16n8k8.row.col.f32.tf32.tf32.f32 "
        "{%0,%1,%2,%3}, {%4,%5,%6,%7}, {%8,%9}, {%0,%1,%2,%3};"
        : "+f"(d[0]), "+f"(d[1]), "+f"(d[2]), "+f"(d[3])
        : "r"(a[0]), "r"(a[1]), "r"(a[2]), "r"(a[3]), "r"(b[0]), "r"(b[1]));
}

// ---------------- init ----------------
__global__ void k_init() {
    int i = blockIdx.x * blockDim.x + threadIdx.x;
    if (i < N_NODES) g_deg[i] = 0;
    if (i < N_GRAPHS) { g_mu[i] = 0u; g_s[i] = 0.0f; }
    if (i < N_GRAPHS * FEAT) g_pool[i] = 0.0f;
}

// ---------------- CSR build (split layout: src=ei[0..E), dst=ei[E..2E)) ------
__global__ void k_hist(const int* __restrict__ ei) {
    int e = blockIdx.x * blockDim.x + threadIdx.x;
    if (e < N_EDGES) atomicAdd(&g_deg[ei[N_EDGES + e]], 1);
}

__global__ void k_scan() {   // single block, 1024 threads
    __shared__ int partial[1024];
    const int T = 1024;
    int t = threadIdx.x;
    int chunk = (N_NODES + T - 1) / T;
    int lo = t * chunk;
    int hi = min(lo + chunk, N_NODES);
    int sum = 0;
    for (int i = lo; i < hi; i++) sum += g_deg[i];
    partial[t] = sum;
    __syncthreads();
    for (int d = 1; d < T; d <<= 1) {
        int v = (t >= d) ? partial[t - d] : 0;
        __syncthreads();
        partial[t] += v;
        __syncthreads();
    }
    int run = (t == 0) ? 0 : partial[t - 1];
    for (int i = lo; i < hi; i++) {
        g_off[i] = run;
        g_cur[i] = run;
        g_cnt[i] = fmaxf((float)g_deg[i], 1.0f);
        run += g_deg[i];
    }
    if (t == T - 1) g_off[N_NODES] = run;
}

__global__ void k_scatter(const int* __restrict__ ei) {
    int e = blockIdx.x * blockDim.x + threadIdx.x;
    if (e < N_EDGES) {
        int pos = atomicAdd(&g_cur[ei[N_EDGES + e]], 1);
        g_csr[pos] = ei[e];
    }
}

// ---------------- mean aggregation: warp per node, float4 lanes --------------
__global__ __launch_bounds__(256) void k_agg(const float* __restrict__ xext, int sel) {
    const float* __restrict__ X = sel_buf(sel, xext);
    int node = (blockIdx.x * blockDim.x + threadIdx.x) >> 5;
    int lane = threadIdx.x & 31;
    if (node >= N_NODES) return;
    int s = g_off[node], e = g_off[node + 1];
    float ax = 0.f, ay = 0.f, az = 0.f, aw = 0.f;
    int i = s;
    for (; i + 2 <= e; i += 2) {
        int n0 = g_csr[i];
        int n1 = g_csr[i + 1];
        float4 v0 = __ldg((const float4*)(X + (size_t)n0 * FEAT + lane * 4));
        float4 v1 = __ldg((const float4*)(X + (size_t)n1 * FEAT + lane * 4));
        ax += v0.x + v1.x; ay += v0.y + v1.y;
        az += v0.z + v1.z; aw += v0.w + v1.w;
    }
    if (i < e) {
        int n0 = g_csr[i];
        float4 v0 = __ldg((const float4*)(X + (size_t)n0 * FEAT + lane * 4));
        ax += v0.x; ay += v0.y; az += v0.z; aw += v0.w;
    }
    float inv = 1.0f / g_cnt[node];
    float4 o = make_float4(ax * inv, ay * inv, az * inv, aw * inv);
    *(float4*)(g_mean + (size_t)node * FEAT + lane * 4) = o;
}

// ---------------- tensor-core fused GEMM: out = relu(g_mean@W1 + A2@W2 + b) --
// 128x128 output tile per CTA, 8 warps (4 M x 2 N), mma.m16n8k8 tf32.
#define GBM 128
#define GBK 32
__global__ __launch_bounds__(256) void k_gemm_tc(
    const float* __restrict__ xext,
    const float* __restrict__ W1, const float* __restrict__ W2,
    const float* __restrict__ bias, int sel, int nrows)
{
    const float* __restrict__ A2 = sel_buf(sel, xext);
    float* __restrict__ out = (sel == 1) ? g_hB : g_hA;

    __shared__ float As[GBM][36];    // pad 36: bank = 4*row+col, conflict-free frags
    __shared__ float Bs[GBK][136];   // pad 136: bank = 8*k+n, conflict-free frags

    int br   = blockIdx.x * GBM;
    int tid  = threadIdx.x;
    int lane = tid & 31;
    int wid  = tid >> 5;
    int wm   = wid & 3;      // warp M slab: rows wm*32 .. +31
    int wn   = wid >> 2;     // warp N half: cols wn*64 .. +63

    float d[2][8][4];
#pragma unroll
    for (int mt = 0; mt < 2; mt++)
#pragma unroll
        for (int nt = 0; nt < 8; nt++)
#pragma unroll
            for (int c = 0; c < 4; c++) d[mt][nt][c] = 0.0f;

    for (int phase = 0; phase < 2; phase++) {
        const float* __restrict__ A = phase ? A2 : (const float*)g_mean;
        const float* __restrict__ W = phase ? W2 : W1;
        for (int k0 = 0; k0 < FEAT; k0 += GBK) {
            // ---- stage A chunk [128 x 32] ----
            {
                int m = tid >> 3;              // 0..31
                int q = (tid & 7) * 4;         // col quad
#pragma unroll
                for (int p = 0; p < 4; p++) {
                    int row  = m + p * 32;
                    int grow = br + row;
                    float4 v = make_float4(0.f, 0.f, 0.f, 0.f);
                    if (grow < nrows)
                        v = *(const float4*)(A + (size_t)grow * FEAT + k0 + q);
                    As[row][q + 0] = tf32r(v.x);
                    As[row][q + 1] = tf32r(v.y);
                    As[row][q + 2] = tf32r(v.z);
                    As[row][q + 3] = tf32r(v.w);
                }
            }
            // ---- stage B chunk [32 x 128] ----
            {
                int r = tid >> 5;              // 0..7
                int c = (tid & 31) * 4;
#pragma unroll
                for (int p = 0; p < 4; p++) {
                    int krow = r + p * 8;
                    float4 v = *(const float4*)(W + (size_t)(k0 + krow) * FEAT + c);
                    float4 o = make_float4(tf32r(v.x), tf32r(v.y), tf32r(v.z), tf32r(v.w));
                    *(float4*)&Bs[krow][c] = o;
                }
            }
            __syncthreads();

#pragma unroll
            for (int ks = 0; ks < 4; ks++) {
                unsigned a[2][4], b[8][2];
                int arow = wm * 32 + (lane >> 2);
                int acol = ks * 8 + (lane & 3);
#pragma unroll
                for (int mt = 0; mt < 2; mt++) {
                    int r0 = arow + mt * 16;
                    a[mt][0] = __float_as_uint(As[r0][acol]);
                    a[mt][1] = __float_as_uint(As[r0 + 8][acol]);
                    a[mt][2] = __float_as_uint(As[r0][acol + 4]);
                    a[mt][3] = __float_as_uint(As[r0 + 8][acol + 4]);
                }
                int bk  = ks * 8 + (lane & 3);
                int bn0 = wn * 64 + (lane >> 2);
#pragma unroll
                for (int nt = 0; nt < 8; nt++) {
                    b[nt][0] = __float_as_uint(Bs[bk][bn0 + nt * 8]);
                    b[nt][1] = __float_as_uint(Bs[bk + 4][bn0 + nt * 8]);
                }
#pragma unroll
                for (int mt = 0; mt < 2; mt++)
#pragma unroll
                    for (int nt = 0; nt < 8; nt++)
                        mma_tf32(d[mt][nt], a[mt], b[nt]);
            }
            __syncthreads();
        }
    }

    // ---- epilogue: bias + relu, float2 stores ----
    int rbase = br + wm * 32 + (lane >> 2);
    int cbase = wn * 64 + (lane & 3) * 2;
#pragma unroll
    for (int nt = 0; nt < 8; nt++) {
        int col = cbase + nt * 8;
        float bv0 = __ldg(&bias[col]);
        float bv1 = __ldg(&bias[col + 1]);
#pragma unroll
        for (int mt = 0; mt < 2; mt++) {
            int r0 = rbase + mt * 16;
            if (r0 < nrows) {
                float2 o;
                o.x = fmaxf(d[mt][nt][0] + bv0, 0.0f);
                o.y = fmaxf(d[mt][nt][1] + bv1, 0.0f);
                *(float2*)(out + (size_t)r0 * FEAT + col) = o;
            }
            int r1 = r0 + 8;
            if (r1 < nrows) {
                float2 o;
                o.x = fmaxf(d[mt][nt][2] + bv0, 0.0f);
                o.y = fmaxf(d[mt][nt][3] + bv1, 0.0f);
                *(float2*)(out + (size_t)r1 * FEAT + col) = o;
            }
        }
    }
}

// ---------------- gate: g_gate[i] = g_hA[i,:]·gate_w + gate_b ----------------
__global__ void k_gate(const float* __restrict__ gate_w,
                       const float* __restrict__ gate_b) {
    int warp = threadIdx.x >> 5;
    int lane = threadIdx.x & 31;
    int node = blockIdx.x * 8 + warp;
    if (node >= N_NODES) return;
    const float* hr = g_hA + (size_t)node * FEAT;
    float4 hv = *(const float4*)(hr + lane * 4);
    float4 wv = *(const float4*)(gate_w + lane * 4);
    float s = hv.x * wv.x + hv.y * wv.y + hv.z * wv.z + hv.w * wv.w;
#pragma unroll
    for (int d = 16; d > 0; d >>= 1) s += __shfl_xor_sync(0xFFFFFFFFu, s, d);
    if (lane == 0) g_gate[node] = s + gate_b[0];
}

__global__ void k_segmax(const int* __restrict__ batch) {
    int i = blockIdx.x * blockDim.x + threadIdx.x;
    if (i < N_NODES) atomicMax(&g_mu[batch[i]], float_to_ordered(g_gate[i]));
}

__global__ void k_expsum(const int* __restrict__ batch) {
    int i = blockIdx.x * blockDim.x + threadIdx.x;
    if (i < N_NODES) {
        int b = batch[i];
        float m = ordered_to_float(g_mu[b]);
        float e = expf(g_gate[i] - m);
        g_gate[i] = e;
        atomicAdd(&g_s[b], e);
    }
}

__global__ void k_pool(const int* __restrict__ batch) {
    int node = blockIdx.x;
    int t = threadIdx.x;
    int b = batch[node];
    float w = g_gate[node];
    atomicAdd(&g_pool[(size_t)b * FEAT + t], w * g_hA[(size_t)node * FEAT + t]);
}

// ---------------- head ----------------
__global__ void k_head(const float* __restrict__ lin1_w, const float* __restrict__ lin1_b,
                       const float* __restrict__ lin2_w, const float* __restrict__ lin2_b,
                       float* __restrict__ out) {
    int g = blockIdx.x;
    int t = threadIdx.x;
    __shared__ float sp[FEAT];
    __shared__ float so[FEAT];
    __shared__ float lg[N_CLASSES];

    float s = g_s[g];
    float p = (s > 0.0f) ? g_pool[(size_t)g * FEAT + t] / s : 0.0f;
    sp[t] = p;
    __syncthreads();

    float acc = lin1_b[t];
#pragma unroll 8
    for (int k = 0; k < FEAT; k++)
        acc = fmaf(sp[k], lin1_w[(size_t)k * FEAT + t], acc);
    so[t] = fmaxf(acc, 0.0f);
    __syncthreads();

    if (t < N_CLASSES) {
        float a = lin2_b[t];
#pragma unroll 8
        for (int k = 0; k < FEAT; k++)
            a = fmaf(so[k], lin2_w[(size_t)k * N_CLASSES + t], a);
        lg[t] = a;
    }
    __syncthreads();

    if (t == 0) {
        float mx = lg[0];
#pragma unroll
        for (int j = 1; j < N_CLASSES; j++) mx = fmaxf(mx, lg[j]);
        float se = 0.0f;
#pragma unroll
        for (int j = 0; j < N_CLASSES; j++) se += expf(lg[j] - mx);
        float l = logf(se);
#pragma unroll
        for (int j = 0; j < N_CLASSES; j++)
            out[(size_t)g * N_CLASSES + j] = lg[j] - mx - l;
    }
}

// ---------------- launch ----------------
extern "C" void kernel_launch(void* const* d_in, const int* in_sizes, int n_in,
                              void* d_out, int out_size) {
    const float* x      = (const float*)d_in[0];
    const int*   ei     = (const int*)  d_in[1];
    const int*   batch  = (const int*)  d_in[2];
    const float* w1l = (const float*)d_in[3];
    const float* b1  = (const float*)d_in[4];
    const float* w1r = (const float*)d_in[5];
    const float* w2l = (const float*)d_in[6];
    const float* b2  = (const float*)d_in[7];
    const float* w2r = (const float*)d_in[8];
    const float* w3l = (const float*)d_in[9];
    const float* b3  = (const float*)d_in[10];
    const float* w3r = (const float*)d_in[11];
    const float* gate_w = (const float*)d_in[12];
    const float* gate_b = (const float*)d_in[13];
    const float* lin1_w = (const float*)d_in[14];
    const float* lin1_b = (const float*)d_in[15];
    const float* lin2_w = (const float*)d_in[16];
    const float* lin2_b = (const float*)d_in[17];
    float* out = (float*)d_out;

    const int TB = 256;
    int init_elems = N_NODES;
    if (N_GRAPHS * FEAT > init_elems) init_elems = N_GRAPHS * FEAT;

    k_init<<<(init_elems + TB - 1) / TB, TB>>>();
    k_hist<<<(N_EDGES + TB - 1) / TB, TB>>>(ei);
    k_scan<<<1, 1024>>>();
    k_scatter<<<(N_EDGES + TB - 1) / TB, TB>>>(ei);

    int agg_blocks  = (N_NODES * 32 + TB - 1) / TB;      // warp per node
    int gemm_blocks = (N_NODES + GBM - 1) / GBM;

    // layer 1: g_hA = relu(mean(x)@w1l + x@w1r + b1)
    k_agg<<<agg_blocks, TB>>>(x, 0);
    k_gemm_tc<<<gemm_blocks, 256>>>(x, w1l, w1r, b1, 0, N_NODES);
    // layer 2: g_hB = relu(mean(g_hA)@w2l + g_hA@w2r + b2)
    k_agg<<<agg_blocks, TB>>>(x, 1);
    k_gemm_tc<<<gemm_blocks, 256>>>(x, w2l, w2r, b2, 1, N_NODES);
    // layer 3: g_hA = relu(mean(g_hB)@w3l + g_hB@w3r + b3)
    k_agg<<<agg_blocks, TB>>>(x, 2);
    k_gemm_tc<<<gemm_blocks, 256>>>(x, w3l, w3r, b3, 2, N_NODES);

    // attentional aggregation over g_hA
    k_gate<<<(N_NODES + 7) / 8, 256>>>(gate_w, gate_b);
    k_segmax<<<(N_NODES + TB - 1) / TB, TB>>>(batch);
    k_expsum<<<(N_NODES + TB - 1) / TB, TB>>>(batch);
    k_pool<<<N_NODES, FEAT>>>(batch);

    // head
    k_head<<<N_GRAPHS, FEAT>>>(lin1_w, lin1_b, lin2_w, lin2_b, out);
}

// round 7
// speedup vs baseline: 1.7721x; 1.0594x over previous
#include <cuda_runtime.h>
#include <cuda_bf16.h>
#include <math.h>

#define N_NODES   100000
#define N_EDGES   1600000
#define FEAT      128
#define N_GRAPHS  512
#define N_CLASSES 10

// ---------------- scratch (device globals; referenced ONLY from device code) --
__device__ int   g_deg[N_NODES];
__device__ int   g_off[N_NODES + 1];
__device__ int   g_cur[N_NODES];
__device__ int   g_csr[N_EDGES];
__device__ float g_cnt[N_NODES];
__device__ int   g_end[N_GRAPHS];         // exclusive end of each graph's node range

__device__ float g_mean[N_NODES * FEAT];
__device__ float g_hA[N_NODES * FEAT];
__device__ float g_hB[N_NODES * FEAT];

__device__ float g_gate[N_NODES];         // gate, then exp(gate - m)

// ---------------- helpers ----------------
__device__ __forceinline__ float tf32r(float x) {   // round-to-nearest tf32
    unsigned r;
    asm("cvt.rna.tf32.f32 %0, %1;" : "=r"(r) : "f"(x));
    return __uint_as_float(r);
}
__device__ __forceinline__ const float* sel_buf(int sel, const float* xext) {
    return sel == 0 ? xext : (sel == 1 ? (const float*)g_hA : (const float*)g_hB);
}
__device__ __forceinline__ void mma_tf32(float* d, const unsigned* a, const unsigned* b) {
    asm volatile(
        "mma.sync.aligned.m16n8k8.row.col.f32.tf32.tf32.f32 "
        "{%0,%1,%2,%3}, {%4,%5,%6,%7}, {%8,%9}, {%0,%1,%2,%3};"
        : "+f"(d[0]), "+f"(d[1]), "+f"(d[2]), "+f"(d[3])
        : "r"(a[0]), "r"(a[1]), "r"(a[2]), "r"(a[3]), "r"(b[0]), "r"(b[1]));
}

// ---------------- init ----------------
__global__ void k_init() {
    int i = blockIdx.x * blockDim.x + threadIdx.x;
    if (i < N_NODES) g_deg[i] = 0;
}

// ---------------- CSR build (split layout: src=ei[0..E), dst=ei[E..2E)) ------
__global__ void k_hist(const int* __restrict__ ei) {
    int e = blockIdx.x * blockDim.x + threadIdx.x;
    if (e < N_EDGES) atomicAdd(&g_deg[ei[N_EDGES + e]], 1);
}

__global__ void k_scan() {   // single block, 1024 threads
    __shared__ int partial[1024];
    const int T = 1024;
    int t = threadIdx.x;
    int chunk = (N_NODES + T - 1) / T;
    int lo = t * chunk;
    int hi = min(lo + chunk, N_NODES);
    int sum = 0;
    for (int i = lo; i < hi; i++) sum += g_deg[i];
    partial[t] = sum;
    __syncthreads();
    for (int d = 1; d < T; d <<= 1) {
        int v = (t >= d) ? partial[t - d] : 0;
        __syncthreads();
        partial[t] += v;
        __syncthreads();
    }
    int run = (t == 0) ? 0 : partial[t - 1];
    for (int i = lo; i < hi; i++) {
        g_off[i] = run;
        g_cur[i] = run;
        g_cnt[i] = fmaxf((float)g_deg[i], 1.0f);
        run += g_deg[i];
    }
    if (t == T - 1) g_off[N_NODES] = run;
}

__global__ void k_scatter(const int* __restrict__ ei) {
    int e = blockIdx.x * blockDim.x + threadIdx.x;
    if (e < N_EDGES) {
        int pos = atomicAdd(&g_cur[ei[N_EDGES + e]], 1);
        g_csr[pos] = ei[e];
    }
}

// ---------------- graph boundaries from sorted batch (no atomics) ------------
__global__ void k_boundary(const int* __restrict__ batch) {
    int i = blockIdx.x * blockDim.x + threadIdx.x;
    if (i >= N_NODES) return;
    int b  = batch[i];
    int bn = (i + 1 < N_NODES) ? batch[i + 1] : N_GRAPHS;
    if (i == 0)
        for (int g = 0; g < b; g++) g_end[g] = 0;    // leading empty graphs
    for (int g = b; g < bn; g++) g_end[g] = i + 1;   // last node of graph b (+ empties)
}

// ---------------- mean aggregation: warp per node, unroll 4 ------------------
__global__ __launch_bounds__(256) void k_agg(const float* __restrict__ xext, int sel) {
    const float* __restrict__ X = sel_buf(sel, xext);
    int node = (blockIdx.x * blockDim.x + threadIdx.x) >> 5;
    int lane = threadIdx.x & 31;
    if (node >= N_NODES) return;
    int s = g_off[node], e = g_off[node + 1];
    float ax = 0.f, ay = 0.f, az = 0.f, aw = 0.f;
    int i = s;
    for (; i + 4 <= e; i += 4) {
        int n0 = g_csr[i], n1 = g_csr[i + 1], n2 = g_csr[i + 2], n3 = g_csr[i + 3];
        float4 v0 = __ldg((const float4*)(X + (size_t)n0 * FEAT + lane * 4));
        float4 v1 = __ldg((const float4*)(X + (size_t)n1 * FEAT + lane * 4));
        float4 v2 = __ldg((const float4*)(X + (size_t)n2 * FEAT + lane * 4));
        float4 v3 = __ldg((const float4*)(X + (size_t)n3 * FEAT + lane * 4));
        ax += (v0.x + v1.x) + (v2.x + v3.x);
        ay += (v0.y + v1.y) + (v2.y + v3.y);
        az += (v0.z + v1.z) + (v2.z + v3.z);
        aw += (v0.w + v1.w) + (v2.w + v3.w);
    }
    for (; i < e; i++) {
        int n0 = g_csr[i];
        float4 v0 = __ldg((const float4*)(X + (size_t)n0 * FEAT + lane * 4));
        ax += v0.x; ay += v0.y; az += v0.z; aw += v0.w;
    }
    float inv = 1.0f / g_cnt[node];
    float4 o = make_float4(ax * inv, ay * inv, az * inv, aw * inv);
    *(float4*)(g_mean + (size_t)node * FEAT + lane * 4) = o;
}

// ---------------- tensor-core fused GEMM with register prefetch --------------
// out = relu(g_mean@W1 + A2@W2 + bias); 128x128 tile/CTA, 8 warps, mma.m16n8k8 tf32
#define GBM 128
#define GBK 32
__global__ __launch_bounds__(256) void k_gemm_tc(
    const float* __restrict__ xext,
    const float* __restrict__ W1, const float* __restrict__ W2,
    const float* __restrict__ bias, int sel, int nrows)
{
    const float* __restrict__ A2 = sel_buf(sel, xext);
    float* __restrict__ out = (sel == 1) ? g_hB : g_hA;
    const float* Aptr[2] = { (const float*)g_mean, A2 };
    const float* Wptr[2] = { W1, W2 };

    __shared__ float As[GBM][36];    // pad 36: conflict-free frag reads
    __shared__ float Bs[GBK][136];   // pad 136

    int row0 = blockIdx.x * GBM;
    int tid  = threadIdx.x;
    int lane = tid & 31;
    int wid  = tid >> 5;
    int wm   = wid & 3;
    int wn   = wid >> 2;

    // staging thread mapping
    int am = tid >> 3;             // 0..31 (A row base)
    int aq = (tid & 7) * 4;        // A col quad
    int brw = tid >> 5;            // 0..7  (B k-row base)
    int bc  = (tid & 31) * 4;      // B col quad

    float4 ar[4], brv[4];

    auto load_chunk = [&](int c) {
        int ph = c >> 2, k0 = (c & 3) * GBK;
        const float* __restrict__ A = Aptr[ph];
        const float* __restrict__ W = Wptr[ph];
#pragma unroll
        for (int p = 0; p < 4; p++) {
            int grow = row0 + am + p * 32;
            ar[p] = (grow < nrows)
                ? *(const float4*)(A + (size_t)grow * FEAT + k0 + aq)
                : make_float4(0.f, 0.f, 0.f, 0.f);
            brv[p] = *(const float4*)(W + (size_t)(k0 + brw + p * 8) * FEAT + bc);
        }
    };

    float d[2][8][4];
#pragma unroll
    for (int mt = 0; mt < 2; mt++)
#pragma unroll
        for (int nt = 0; nt < 8; nt++)
#pragma unroll
            for (int c = 0; c < 4; c++) d[mt][nt][c] = 0.0f;

    load_chunk(0);
    for (int c = 0; c < 8; c++) {
        // store staged regs -> smem (tf32 convert)
#pragma unroll
        for (int p = 0; p < 4; p++) {
            int row = am + p * 32;
            As[row][aq + 0] = tf32r(ar[p].x);
            As[row][aq + 1] = tf32r(ar[p].y);
            As[row][aq + 2] = tf32r(ar[p].z);
            As[row][aq + 3] = tf32r(ar[p].w);
            int krow = brw + p * 8;
            Bs[krow][bc + 0] = tf32r(brv[p].x);
            Bs[krow][bc + 1] = tf32r(brv[p].y);
            Bs[krow][bc + 2] = tf32r(brv[p].z);
            Bs[krow][bc + 3] = tf32r(brv[p].w);
        }
        __syncthreads();
        if (c < 7) load_chunk(c + 1);   // overlap next-chunk loads with MMAs

#pragma unroll
        for (int ks = 0; ks < 4; ks++) {
            unsigned a[2][4], b[8][2];
            int arow = wm * 32 + (lane >> 2);
            int acol = ks * 8 + (lane & 3);
#pragma unroll
            for (int mt = 0; mt < 2; mt++) {
                int r0 = arow + mt * 16;
                a[mt][0] = __float_as_uint(As[r0][acol]);
                a[mt][1] = __float_as_uint(As[r0 + 8][acol]);
                a[mt][2] = __float_as_uint(As[r0][acol + 4]);
                a[mt][3] = __float_as_uint(As[r0 + 8][acol + 4]);
            }
            int bk  = ks * 8 + (lane & 3);
            int bn0 = wn * 64 + (lane >> 2);
#pragma unroll
            for (int nt = 0; nt < 8; nt++) {
                b[nt][0] = __float_as_uint(Bs[bk][bn0 + nt * 8]);
                b[nt][1] = __float_as_uint(Bs[bk + 4][bn0 + nt * 8]);
            }
#pragma unroll
            for (int mt = 0; mt < 2; mt++)
#pragma unroll
                for (int nt = 0; nt < 8; nt++)
                    mma_tf32(d[mt][nt], a[mt], b[nt]);
        }
        __syncthreads();
    }

    // ---- epilogue: bias + relu, float2 stores ----
    int rbase = row0 + wm * 32 + (lane >> 2);
    int cbase = wn * 64 + (lane & 3) * 2;
#pragma unroll
    for (int nt = 0; nt < 8; nt++) {
        int col = cbase + nt * 8;
        float bv0 = __ldg(&bias[col]);
        float bv1 = __ldg(&bias[col + 1]);
#pragma unroll
        for (int mt = 0; mt < 2; mt++) {
            int r0 = rbase + mt * 16;
            if (r0 < nrows) {
                float2 o;
                o.x = fmaxf(d[mt][nt][0] + bv0, 0.0f);
                o.y = fmaxf(d[mt][nt][1] + bv1, 0.0f);
                *(float2*)(out + (size_t)r0 * FEAT + col) = o;
            }
            int r1 = r0 + 8;
            if (r1 < nrows) {
                float2 o;
                o.x = fmaxf(d[mt][nt][2] + bv0, 0.0f);
                o.y = fmaxf(d[mt][nt][3] + bv1, 0.0f);
                *(float2*)(out + (size_t)r1 * FEAT + col) = o;
            }
        }
    }
}

// ---------------- fused attention pooling + MLP head (1 block / graph) -------
__global__ __launch_bounds__(128) void k_attnpool(
    const float* __restrict__ gate_w, const float* __restrict__ gate_b,
    const float* __restrict__ lin1_w, const float* __restrict__ lin1_b,
    const float* __restrict__ lin2_w, const float* __restrict__ lin2_b,
    float* __restrict__ out)
{
    int g  = blockIdx.x;
    int lo = (g == 0) ? 0 : g_end[g - 1];
    int hi = g_end[g];
    int t = threadIdx.x, warp = t >> 5, lane = t & 31;

    __shared__ float red4[4];
    __shared__ float s_m, s_s;
    __shared__ float sp[FEAT];
    __shared__ float so[FEAT];
    __shared__ float lg[N_CLASSES];

    // ---- pass 1: gate per node + block max ----
    float4 wv = *(const float4*)(gate_w + lane * 4);
    float gb = __ldg(&gate_b[0]);
    float lmax = -1e30f;
    for (int node = lo + warp; node < hi; node += 4) {
        float4 hv = *(const float4*)(g_hA + (size_t)node * FEAT + lane * 4);
        float s = hv.x * wv.x + hv.y * wv.y + hv.z * wv.z + hv.w * wv.w;
#pragma unroll
        for (int d = 16; d > 0; d >>= 1) s += __shfl_xor_sync(0xFFFFFFFFu, s, d);
        s += gb;
        if (lane == 0) g_gate[node] = s;
        lmax = fmaxf(lmax, s);
    }
    if (lane == 0) red4[warp] = lmax;
    __syncthreads();
    if (t == 0)
        s_m = fmaxf(fmaxf(red4[0], red4[1]), fmaxf(red4[2], red4[3]));
    __syncthreads();
    float m = s_m;

    // ---- pass 2: exp + sum ----
    float part = 0.0f;
    for (int node = lo + t; node < hi; node += 128) {
        float e = expf(g_gate[node] - m);
        g_gate[node] = e;
        part += e;
    }
#pragma unroll
    for (int d = 16; d > 0; d >>= 1) part += __shfl_xor_sync(0xFFFFFFFFu, part, d);
    if (lane == 0) red4[warp] = part;
    __syncthreads();
    if (t == 0) s_s = red4[0] + red4[1] + red4[2] + red4[3];
    __syncthreads();
    float s = s_s;
    float invs = (s > 0.0f) ? 1.0f / s : 0.0f;

    // ---- pass 3: weighted feature sum (thread t owns feature t) ----
    float acc = 0.0f;
#pragma unroll 4
    for (int node = lo; node < hi; node++)
        acc += g_gate[node] * g_hA[(size_t)node * FEAT + t];
    sp[t] = acc * invs;
    __syncthreads();

    // ---- head: relu(lin1) -> lin2 -> log_softmax ----
    float h1 = lin1_b[t];
#pragma unroll 8
    for (int k = 0; k < FEAT; k++)
        h1 = fmaf(sp[k], lin1_w[(size_t)k * FEAT + t], h1);
    so[t] = fmaxf(h1, 0.0f);
    __syncthreads();

    if (t < N_CLASSES) {
        float a = lin2_b[t];
#pragma unroll 8
        for (int k = 0; k < FEAT; k++)
            a = fmaf(so[k], lin2_w[(size_t)k * N_CLASSES + t], a);
        lg[t] = a;
    }
    __syncthreads();

    if (t == 0) {
        float mx = lg[0];
#pragma unroll
        for (int j = 1; j < N_CLASSES; j++) mx = fmaxf(mx, lg[j]);
        float se = 0.0f;
#pragma unroll
        for (int j = 0; j < N_CLASSES; j++) se += expf(lg[j] - mx);
        float l = logf(se);
#pragma unroll
        for (int j = 0; j < N_CLASSES; j++)
            out[(size_t)g * N_CLASSES + j] = lg[j] - mx - l;
    }
}

// ---------------- launch ----------------
extern "C" void kernel_launch(void* const* d_in, const int* in_sizes, int n_in,
                              void* d_out, int out_size) {
    const float* x      = (const float*)d_in[0];
    const int*   ei     = (const int*)  d_in[1];
    const int*   batch  = (const int*)  d_in[2];
    const float* w1l = (const float*)d_in[3];
    const float* b1  = (const float*)d_in[4];
    const float* w1r = (const float*)d_in[5];
    const float* w2l = (const float*)d_in[6];
    const float* b2  = (const float*)d_in[7];
    const float* w2r = (const float*)d_in[8];
    const float* w3l = (const float*)d_in[9];
    const float* b3  = (const float*)d_in[10];
    const float* w3r = (const float*)d_in[11];
    const float* gate_w = (const float*)d_in[12];
    const float* gate_b = (const float*)d_in[13];
    const float* lin1_w = (const float*)d_in[14];
    const float* lin1_b = (const float*)d_in[15];
    const float* lin2_w = (const float*)d_in[16];
    const float* lin2_b = (const float*)d_in[17];
    float* out = (float*)d_out;

    const int TB = 256;

    k_init<<<(N_NODES + TB - 1) / TB, TB>>>();
    k_hist<<<(N_EDGES + TB - 1) / TB, TB>>>(ei);
    k_scan<<<1, 1024>>>();
    k_scatter<<<(N_EDGES + TB - 1) / TB, TB>>>(ei);
    k_boundary<<<(N_NODES + TB - 1) / TB, TB>>>(batch);

    int agg_blocks  = (N_NODES * 32 + TB - 1) / TB;
    int gemm_blocks = (N_NODES + GBM - 1) / GBM;

    // layer 1: g_hA = relu(mean(x)@w1l + x@w1r + b1)
    k_agg<<<agg_blocks, TB>>>(x, 0);
    k_gemm_tc<<<gemm_blocks, 256>>>(x, w1l, w1r, b1, 0, N_NODES);
    // layer 2: g_hB = relu(mean(g_hA)@w2l + g_hA@w2r + b2)
    k_agg<<<agg_blocks, TB>>>(x, 1);
    k_gemm_tc<<<gemm_blocks, 256>>>(x, w2l, w2r, b2, 1, N_NODES);
    // layer 3: g_hA = relu(mean(g_hB)@w3l + g_hB@w3r + b3)
    k_agg<<<agg_blocks, TB>>>(x, 2);
    k_gemm_tc<<<gemm_blocks, 256>>>(x, w3l, w3r, b3, 2, N_NODES);

    // fused attentional aggregation + head
    k_attnpool<<<N_GRAPHS, 128>>>(gate_w, gate_b, lin1_w, lin1_b,
                                  lin2_w, lin2_b, out);
}